// round 6
// baseline (speedup 1.0000x reference)
#include <cuda_runtime.h>
#include <cstdint>

// Problem constants (fixed by the reference: B=4, N=262144, G=128)
#define NBATCH 4
#define NPART  262144          // 2^18
#define GDIM   128
#define BOUNDC 3

__constant__ float kDT = 5e-4f;

// Fully fused grid_op + g2p with interior fast path.
// Each z-row of 3 nodes (9 floats, 36B) is fetched with 3 aligned LDG.128
// covering a 48B window; r = (3s)&3 is uniform per particle so extraction is
// a 2-predicate SEL tree. Particles whose stencil provably touches no
// boundary band (nodes 0..2 and 125..127) and no floor band skip all grid_op
// math (~84% of particles).
__global__ __launch_bounds__(256, 5)
void fused_kernel(const float* __restrict__ x,
                  const float* __restrict__ friction,
                  const float* __restrict__ pred,
                  const float* __restrict__ collider_floor,
                  const int*   __restrict__ statics,
                  float* __restrict__ out)
{
    const int pid = blockIdx.x * blockDim.x + threadIdx.x;
    const int total = NBATCH * NPART;
    if (pid >= total) return;

    const int b = pid >> 18;
    const float dx = 1.0f / (float)GDIM;
    const float inv_dx = (float)GDIM;

    const float x0 = x[pid * 3 + 0];
    const float x1 = x[pid * 3 + 1];
    const float x2 = x[pid * 3 + 2];

    const float mu  = friction[b];
    const float thr = collider_floor[b] + (float)BOUNDC * dx;

    // ---- stencil setup ----
    float w0[3], w1[3], w2[3];
    int bx, by, bz;
    {
        const float p0f = x0 * inv_dx;
        const float p1f = x1 * inv_dx;
        const float p2f = x2 * inv_dx;
        bx = (int)floorf(p0f - 0.5f);
        by = (int)floorf(p1f - 0.5f);
        bz = (int)floorf(p2f - 0.5f);
        const float f0 = p0f - (float)bx;
        const float f1 = p1f - (float)by;
        const float f2 = p2f - (float)bz;

        w0[0] = 0.5f * (1.5f - f0) * (1.5f - f0);
        w0[1] = 0.75f - (f0 - 1.0f) * (f0 - 1.0f);
        w0[2] = 0.5f * (f0 - 0.5f) * (f0 - 0.5f);
        w1[0] = 0.5f * (1.5f - f1) * (1.5f - f1);
        w1[1] = 0.75f - (f1 - 1.0f) * (f1 - 1.0f);
        w1[2] = 0.5f * (f1 - 0.5f) * (f1 - 0.5f);
        w2[0] = 0.5f * (1.5f - f2) * (1.5f - f2);
        w2[1] = 0.75f - (f2 - 1.0f) * (f2 - 1.0f);
        w2[2] = 0.5f * (f2 - 0.5f) * (f2 - 0.5f);
    }

    const float4* __restrict__ g4 =
        (const float4*)(pred) + (size_t)b * (GDIM * GDIM * GDIM * 3 / 4);

    float accx = 0.0f, accy = 0.0f, accz = 0.0f;

    // Interior test: stencil nodes b*..b*+2 must avoid the clamp bands
    // {0,1,2} and {125,126,127}  ->  3 <= b* <= 122, and the whole y-range
    // must be strictly above the floor-contact threshold.
    const bool interior =
        (bx >= BOUNDC) & (bx <= GDIM - BOUNDC - 3) &
        (by >= BOUNDC) & (by <= GDIM - BOUNDC - 3) &
        (bz >= BOUNDC) & (bz <= GDIM - BOUNDC - 3) &
        ((float)by * dx > thr);

    if (interior) {
        // ---------------- fast path: pure gather ----------------
        const int s3 = 3 * bz;
        const int r  = s3 & 3;
        const bool p0s = (r & 1) != 0;
        const bool p1s = (r & 2) != 0;
        const int sq = s3 >> 2;

        #pragma unroll
        for (int i = 0; i < 3; i++) {
            const int rowbase = ((bx + i) * GDIM + by) * 96 + sq;
            #pragma unroll
            for (int j = 0; j < 3; j++) {
                const int f4 = rowbase + j * 96;
                const float4 q0 = __ldg(g4 + f4 + 0);
                const float4 q1 = __ldg(g4 + f4 + 1);
                const float4 q2 = __ldg(g4 + f4 + 2);
                const float wij = w0[i] * w1[j];

                const float wq[12] = {q0.x, q0.y, q0.z, q0.w,
                                      q1.x, q1.y, q1.z, q1.w,
                                      q2.x, q2.y, q2.z, q2.w};
                float v[9];
                #pragma unroll
                for (int t = 0; t < 9; t++) {
                    const float a  = p0s ? wq[t + 1] : wq[t];
                    const float bb = p0s ? wq[t + 3] : wq[t + 2];
                    v[t] = p1s ? bb : a;
                }
                #pragma unroll
                for (int t = 0; t < 3; t++) {
                    const float w = wij * w2[t];
                    accx = fmaf(w, v[3 * t + 0], accx);
                    accy = fmaf(w, v[3 * t + 1], accy);
                    accz = fmaf(w, v[3 * t + 2], accz);
                }
            }
        }
    } else {
        // ---------------- slow path: full grid_op ----------------
        int i0[3], i1[3];
        #pragma unroll
        for (int c = 0; c < 3; c++) {
            i0[c] = min(max(bx + c, 0), GDIM - 1);
            i1[c] = min(max(by + c, 0), GDIM - 1);
        }
        const int s = min(max(bz, 0), GDIM - 3);
        float Wz[3] = {0.0f, 0.0f, 0.0f};
        #pragma unroll
        for (int k = 0; k < 3; k++) {
            const int idx = min(max(bz + k, 0), GDIM - 1) - s;
            #pragma unroll
            for (int t = 0; t < 3; t++)
                Wz[t] += (idx == t) ? w2[k] : 0.0f;
        }

        const int s3 = 3 * s;
        const int r  = s3 & 3;
        const bool p0s = (r & 1) != 0;
        const bool p1s = (r & 2) != 0;
        const int sq = s3 >> 2;

        bool zlow[3], zhigh[3];
        #pragma unroll
        for (int t = 0; t < 3; t++) {
            const int gk = s + t;
            zlow[t]  = gk < BOUNDC;
            zhigh[t] = gk >= GDIM - BOUNDC;
        }

        #pragma unroll
        for (int i = 0; i < 3; i++) {
            const int gi = i0[i];
            const bool xlow  = gi < BOUNDC;
            const bool xhigh = gi >= GDIM - BOUNDC;
            #pragma unroll
            for (int j = 0; j < 3; j++) {
                const int gj = i1[j];
                const float wij = w0[i] * w1[j];
                const bool nearf = ((float)gj * dx) <= thr;
                const bool ylow  = gj < BOUNDC;
                const bool yhigh = gj >= GDIM - BOUNDC;

                const int f4 = (gi * GDIM + gj) * 96 + sq;
                const float4 q0 = __ldg(g4 + f4 + 0);
                const float4 q1 = __ldg(g4 + f4 + 1);
                const float4 q2 = __ldg(g4 + f4 + 2);

                const float wq[12] = {q0.x, q0.y, q0.z, q0.w,
                                      q1.x, q1.y, q1.z, q1.w,
                                      q2.x, q2.y, q2.z, q2.w};
                float v[9];
                #pragma unroll
                for (int t = 0; t < 9; t++) {
                    const float a  = p0s ? wq[t + 1] : wq[t];
                    const float bb = p0s ? wq[t + 3] : wq[t + 2];
                    v[t] = p1s ? bb : a;
                }

                #pragma unroll
                for (int t = 0; t < 3; t++) {
                    float vx_ = v[3 * t + 0];
                    float vy_ = v[3 * t + 1];
                    float vz_ = v[3 * t + 2];

                    if (nearf && vy_ < 0.0f) {
                        const float rinv = rsqrtf(vx_ * vx_ + vz_ * vz_ + 1e-10f);
                        const float sc = fmaxf(0.0f, fmaf(mu * vy_, rinv, 1.0f));
                        vx_ *= sc; vz_ *= sc; vy_ = 0.0f;
                    }
                    if ((xlow && vx_ < 0.0f) || (xhigh && vx_ > 0.0f)) vx_ = 0.0f;
                    if ((ylow && vy_ < 0.0f) || (yhigh && vy_ > 0.0f)) vy_ = 0.0f;
                    if ((zlow[t] && vz_ < 0.0f) || (zhigh[t] && vz_ > 0.0f)) vz_ = 0.0f;

                    const float w = wij * Wz[t];
                    accx = fmaf(w, vx_, accx);
                    accy = fmaf(w, vy_, accy);
                    accz = fmaf(w, vz_, accz);
                }
            }
        }
    }

    const float m = (float)statics[pid];
    accx *= m; accy *= m; accz *= m;

    float* __restrict__ out_x = out;
    float* __restrict__ out_v = out + (size_t)total * 3;

    out_x[pid * 3 + 0] = fmaf(kDT, accx, x0);
    out_x[pid * 3 + 1] = fmaf(kDT, accy, x1);
    out_x[pid * 3 + 2] = fmaf(kDT, accz, x2);
    out_v[pid * 3 + 0] = accx;
    out_v[pid * 3 + 1] = accy;
    out_v[pid * 3 + 2] = accz;
}

extern "C" void kernel_launch(void* const* d_in, const int* in_sizes, int n_in,
                              void* d_out, int out_size)
{
    // metadata order: x, v, friction, pred, collider_floor, statics_enabled, step
    const float* x              = (const float*)d_in[0];
    const float* friction       = (const float*)d_in[2];
    const float* pred           = (const float*)d_in[3];
    const float* collider_floor = (const float*)d_in[4];
    const int*   statics        = (const int*)d_in[5];

    float* out = (float*)d_out;

    const int total = NBATCH * NPART;
    const int threads = 256;
    fused_kernel<<<(total + threads - 1) / threads, threads>>>(
        x, friction, pred, collider_floor, statics, out);
}